// round 17
// baseline (speedup 1.0000x reference)
#include <cuda_runtime.h>
#include <stdint.h>

// Problem constants (from reference)
#define GX 352
#define GY 400
#define GZ 1
#define NB 4
#define NSEG (NB * GZ * GY * GX)    // 563200
#define NC 4
#define NP 2000000

// Output layout: [mean: NSEG*NC floats][counts: NSEG floats]
#define OUT_TOTAL (NSEG * (NC + 1))          // 2816000 floats
#define OUT_BYTES ((size_t)OUT_TOTAL * 4)    // 11,264,000 bytes (16B multiple)

// Zero kernel geometry: one wave of 148 blocks, each covers a contiguous slice
// via TMA bulk stores from a zeroed SMEM staging buffer.
#define ZERO_BLOCKS 148
#define ZERO_SMEM   32768
#define ZERO_CHUNK  76112   // ceil(OUT_BYTES/148) rounded up to 16B -> 148*76112 >= OUT_BYTES

__device__ __forceinline__ void red_add_v4(float* dst, float4 f) {
    asm volatile("red.global.add.v4.f32 [%0], {%1, %2, %3, %4};"
                 :: "l"(dst), "f"(f.x), "f"(f.y), "f"(f.z), "f"(f.w)
                 : "memory");
}
__device__ __forceinline__ void red_add_1(float* dst) {
    asm volatile("red.global.add.f32 [%0], %1;"
                 :: "l"(dst), "f"(1.0f) : "memory");
}

// ---------------------------------------------------------------------------
// Kernel 1: zero d_out via cp.async.bulk (SMEM -> GMEM). Bypasses the STG
// issue-cost floor (~12 cyc per STG.128) that made the STG zero kernel 5.2us;
// bulk stores run at the LTS cap (~6300 B/cyc -> ~1us for 11.3MB).
// ---------------------------------------------------------------------------
__global__ void __launch_bounds__(256)
zero_out_kernel(char* __restrict__ out) {
    __shared__ __align__(16) char zbuf[ZERO_SMEM];

    // fill staging buffer with zeros (128-bit STS, one pass)
    for (int i = threadIdx.x * 16; i < ZERO_SMEM; i += 256 * 16)
        *(float4*)(zbuf + i) = make_float4(0.f, 0.f, 0.f, 0.f);
    __syncthreads();

    if (threadIdx.x == 0) {
        // make the generic-proxy STS visible to the async proxy
        asm volatile("fence.proxy.async.shared::cta;" ::: "memory");

        uint32_t src;
        asm("{ .reg .u64 t; cvta.to.shared.u64 t, %1; cvt.u32.u64 %0, t; }"
            : "=r"(src) : "l"(zbuf));

        size_t start = (size_t)blockIdx.x * ZERO_CHUNK;
        size_t end   = start + ZERO_CHUNK;
        if (end > OUT_BYTES) end = OUT_BYTES;

        for (size_t p = start; p < end; p += ZERO_SMEM) {
            uint32_t sz = (uint32_t)((end - p) < ZERO_SMEM ? (end - p) : ZERO_SMEM);
            asm volatile(
                "cp.async.bulk.global.shared::cta.bulk_group [%0], [%1], %2;"
                :: "l"(out + p), "r"(src), "r"(sz) : "memory");
        }
        asm volatile("cp.async.bulk.commit_group;" ::: "memory");
        asm volatile("cp.async.bulk.wait_group 0;" ::: "memory");
    }
}

// ---------------------------------------------------------------------------
// Kernel 2: scatter-add directly into d_out. One point per thread (measured
// best). PDL-dependent on the zero kernel: the long-latency input loads are
// issued BEFORE gridDependencySynchronize (independent of d_out), so the
// zeroing overlaps the load ramp; only the REDs wait for zeros.
// GZ == 1 -> seg = (b*GY + y)*GX + x.
// ---------------------------------------------------------------------------
__global__ void __launch_bounds__(256)
scatter_add_kernel(const float4* __restrict__ features,
                   const int4*   __restrict__ coors,
                   float*        __restrict__ out) {
    int i = blockIdx.x * blockDim.x + threadIdx.x;

    int4   c = make_int4(0, 0, 0, 0);
    float4 f = make_float4(0.f, 0.f, 0.f, 0.f);
    bool active = (i < NP);
    if (active) {
        c = coors[i];
        f = features[i];
    }

    cudaGridDependencySynchronize();

    if (active) {
        int seg = (c.x * GY + c.z) * GX + c.w;
        red_add_v4(out + (size_t)seg * NC, f);
        red_add_1(out + (size_t)NSEG * NC + seg);
    }
}

// ---------------------------------------------------------------------------
// Kernel 3: divide in place. One segment per thread. Counts are already
// final in d_out; just scale the sums region (L2-hot from the REDs).
// PDL-dependent on the scatter.
// ---------------------------------------------------------------------------
__global__ void __launch_bounds__(256)
divide_kernel(float* __restrict__ out) {
    int seg = blockIdx.x * blockDim.x + threadIdx.x;

    cudaGridDependencySynchronize();

    if (seg >= NSEG) return;

    float4* sums = (float4*)out;
    float4 s  = sums[seg];
    float cnt = out[(size_t)NSEG * NC + seg];

    float inv = 1.0f / fmaxf(cnt, 1.0f);
    s.x *= inv; s.y *= inv; s.z *= inv; s.w *= inv;
    sums[seg] = s;
}

// ---------------------------------------------------------------------------
// Launcher: zero (bulk) -> scatter (PDL) -> divide (PDL).
// ---------------------------------------------------------------------------
static void launch_pdl(void* func, dim3 grid, dim3 block, void** args) {
    cudaLaunchConfig_t cfg = {};
    cfg.gridDim = grid;
    cfg.blockDim = block;
    cfg.dynamicSmemBytes = 0;
    cfg.stream = 0;
    cudaLaunchAttribute attrs[1];
    attrs[0].id = cudaLaunchAttributeProgrammaticStreamSerialization;
    attrs[0].val.programmaticStreamSerializationAllowed = 1;
    cfg.attrs = attrs;
    cfg.numAttrs = 1;
    cudaLaunchKernelExC(&cfg, func, args);
}

extern "C" void kernel_launch(void* const* d_in, const int* in_sizes, int n_in,
                              void* d_out, int out_size) {
    const float4* features = (const float4*)d_in[0];  // (NP, 4) fp32
    const int4*   coors    = (const int4*)d_in[1];    // (NP, 4) int32
    float* out = (float*)d_out;

    // 1. zero d_out via TMA bulk stores
    zero_out_kernel<<<ZERO_BLOCKS, 256>>>((char*)d_out);

    // 2. scatter-add (PDL on zero; input loads overlap the zeroing)
    {
        int blocks = (NP + 255) / 256;
        void* args[3] = { (void*)&features, (void*)&coors, (void*)&out };
        launch_pdl((void*)scatter_add_kernel, dim3(blocks), dim3(256), args);
    }

    // 3. divide in place (PDL on scatter)
    {
        int blocks = (NSEG + 255) / 256;
        void* args[1] = { (void*)&out };
        launch_pdl((void*)divide_kernel, dim3(blocks), dim3(256), args);
    }
}